// round 11
// baseline (speedup 1.0000x reference)
#include <cuda_runtime.h>
#include <cstdint>
#include <cstddef>

#define NN   100000   // nodes (max)
#define HH   96       // hidden
#define AA   32       // attn dim
#define EE   500000   // edges per type (max)
#define PCPAD 640     // padded GEMM col count

// ---------------- device scratch ----------------------------------------------
__device__ float g_PA[(size_t)NN * 288];        // A0|A1|A2 per row (gathered by agg)
__device__ float g_PB[(size_t)NN * 288];        // B0|B1|B2 per row (streamed)
__device__ float g_PE[(size_t)NN * 4];          // el0,er0,el1,er1 (L2-hot gathers)
__device__ float g_WpackT[HH * PCPAD];          // k-major: [k][j]
__device__ float g_CB[3 * HH];
__device__ float g_w0[EE];
__device__ float g_w1[EE];
__device__ float g_Xm[(size_t)NN * 288];        // [msg0 | msg1 | msg2]
__device__ int   g_deg[3 * NN];
__device__ int   g_start[3 * NN];
__device__ int   g_cur[3 * NN];
__device__ int   g_bsum[128];
__device__ int   g_csr[3 * EE];

// ---------------- packed f32x2 helpers -----------------------------------------
__device__ __forceinline__ unsigned long long pk2(float lo, float hi) {
    unsigned long long r;
    asm("mov.b64 %0, {%1, %2};" : "=l"(r) : "f"(lo), "f"(hi));
    return r;
}
__device__ __forceinline__ void upk2(unsigned long long v, float& lo, float& hi) {
    asm("mov.b64 {%0, %1}, %2;" : "=f"(lo), "=f"(hi) : "l"(v));
}
__device__ __forceinline__ void fma2(unsigned long long& d, unsigned long long a, unsigned long long b) {
    asm("fma.rn.f32x2 %0, %1, %2, %3;" : "=l"(d) : "l"(a), "l"(b), "l"(d));
}
__device__ __forceinline__ void cp_async16(void* smem, const void* gmem) {
    unsigned s = (unsigned)__cvta_generic_to_shared(smem);
    asm volatile("cp.async.cg.shared.global [%0], [%1], 16;" :: "r"(s), "l"(gmem));
}
__device__ __forceinline__ void cp_commit() { asm volatile("cp.async.commit_group;"); }
__device__ __forceinline__ void cp_wait0()  { asm volatile("cp.async.wait_group 0;"); }

// ---------------- zero init (deg + cur only) -----------------------------------
__global__ void zero_kernel(int M3) {
    int i = blockIdx.x * blockDim.x + threadIdx.x;
    int stride = gridDim.x * blockDim.x;
    for (int k = i; k < M3; k += stride) { g_deg[k] = 0; g_cur[k] = 0; }
}

// ---------------- weight packing (k-major, A|B|attn column order) --------------
__global__ void pack_w_kernel(const float* __restrict__ Wm0, const float* __restrict__ Wm1,
                              const float* __restrict__ Wm2,
                              const float* __restrict__ Wn0, const float* __restrict__ Wa0,
                              const float* __restrict__ Wn1, const float* __restrict__ Wa1) {
    int gid = blockIdx.x * blockDim.x + threadIdx.x;
    if (gid >= PCPAD * HH) return;
    int j = gid / HH;     // output column
    int k = gid % HH;     // input feature
    float v = 0.f;
    if (j < 288) {                      // A-blocks: src part, rows [0,96)
        int t = j / HH;
        int jj = j % HH;
        const float* Wm = (t == 0) ? Wm0 : (t == 1) ? Wm1 : Wm2;
        v = Wm[(size_t)k * HH + jj];
    } else if (j < 576) {               // B-blocks: dst part, rows [96,192)
        int t = (j - 288) / HH;
        int jj = (j - 288) % HH;
        const float* Wm = (t == 0) ? Wm0 : (t == 1) ? Wm1 : Wm2;
        v = Wm[(size_t)(HH + k) * HH + jj];
    } else if (j < 580) {               // attn: el0,er0,el1,er1
        int q = j - 576;
        const float* Wn = (q < 2) ? Wn0 : Wn1;
        const float* Wa = (q < 2) ? Wa0 : Wa1;
        int off = (q & 1) * AA;
        float s = 0.f;
        #pragma unroll
        for (int a = 0; a < AA; a++) s += Wn[(size_t)k * AA + a] * Wa[off + a];
        v = s;
    }
    g_WpackT[(size_t)k * PCPAD + j] = v;
}

__global__ void pack_c_kernel(const float* __restrict__ Wm0, const float* __restrict__ bm0,
                              const float* __restrict__ ef0,
                              const float* __restrict__ Wm1, const float* __restrict__ bm1,
                              const float* __restrict__ ef1,
                              const float* __restrict__ Wm2, const float* __restrict__ bm2,
                              const float* __restrict__ ef2) {
    int gid = threadIdx.x;
    if (gid >= 3 * HH) return;
    int t = gid / HH, j = gid % HH;
    const float* Wm = (t == 0) ? Wm0 : (t == 1) ? Wm1 : Wm2;
    const float* bm = (t == 0) ? bm0 : (t == 1) ? bm1 : bm2;
    const float* ef = (t == 0) ? ef0 : (t == 1) ? ef1 : ef2;
    float s = bm[j];
    #pragma unroll
    for (int d = 0; d < 16; d++) s += ef[d] * Wm[(size_t)(192 + d) * HH + j];
    g_CB[gid] = s;
}

// ---------------- GEMM 1: [PA|PB|PE] = h @ Wcat (double-buffered) --------------
__global__ void __launch_bounds__(256) gemm_p_kernel(const float* __restrict__ h, int Nn) {
    __shared__ float As[2][16][132];
    __shared__ float Bs[2][16][132];
    const int bm = blockIdx.y * 128;
    const int bn = blockIdx.x * 128;
    const int tid = threadIdx.x;
    const int tr = (tid >> 4) << 2;
    const int tc = (tid & 15) << 2;
    unsigned long long acc[8][4];
    #pragma unroll
    for (int i = 0; i < 8; i++)
        #pragma unroll
        for (int j = 0; j < 4; j++) acc[i][j] = 0ull;

    float4 pa[2];
    #pragma unroll
    for (int it = 0; it < 2; it++) {
        int q = tid + it * 256;
        int k = q >> 5;
        int c4 = (q & 31) << 2;
        cp_async16(&Bs[0][k][c4], &g_WpackT[(size_t)k * PCPAD + bn + c4]);
    }
    cp_commit();
    #pragma unroll
    for (int it = 0; it < 2; it++) {
        int q = tid + it * 256;
        int row = q >> 2, kq = (q & 3) << 2;
        int grow = bm + row;
        pa[it] = (grow < Nn) ? *reinterpret_cast<const float4*>(&h[(size_t)grow * HH + kq])
                             : make_float4(0.f, 0.f, 0.f, 0.f);
    }
    #pragma unroll
    for (int it = 0; it < 2; it++) {
        int q = tid + it * 256;
        int row = q >> 2, kq = (q & 3) << 2;
        As[0][kq + 0][row] = pa[it].x; As[0][kq + 1][row] = pa[it].y;
        As[0][kq + 2][row] = pa[it].z; As[0][kq + 3][row] = pa[it].w;
    }
    cp_wait0();
    __syncthreads();

    int b = 0;
    for (int k0 = 0; k0 < HH; k0 += 16) {
        bool more = (k0 + 16 < HH);
        if (more) {
            #pragma unroll
            for (int it = 0; it < 2; it++) {
                int q = tid + it * 256;
                int k = q >> 5;
                int c4 = (q & 31) << 2;
                cp_async16(&Bs[b ^ 1][k][c4], &g_WpackT[(size_t)(k0 + 16 + k) * PCPAD + bn + c4]);
            }
            cp_commit();
            #pragma unroll
            for (int it = 0; it < 2; it++) {
                int q = tid + it * 256;
                int row = q >> 2, kq = (q & 3) << 2;
                int grow = bm + row;
                pa[it] = (grow < Nn) ? *reinterpret_cast<const float4*>(&h[(size_t)grow * HH + k0 + 16 + kq])
                                     : make_float4(0.f, 0.f, 0.f, 0.f);
            }
        }
        #pragma unroll
        for (int kk = 0; kk < 16; kk++) {
            float4 a0 = *reinterpret_cast<const float4*>(&As[b][kk][tr]);
            float4 a1 = *reinterpret_cast<const float4*>(&As[b][kk][tr + 64]);
            float4 b0 = *reinterpret_cast<const float4*>(&Bs[b][kk][tc]);
            float4 b1 = *reinterpret_cast<const float4*>(&Bs[b][kk][tc + 64]);
            unsigned long long bb[4] = {pk2(b0.x, b0.y), pk2(b0.z, b0.w),
                                        pk2(b1.x, b1.y), pk2(b1.z, b1.w)};
            float aa[8] = {a0.x, a0.y, a0.z, a0.w, a1.x, a1.y, a1.z, a1.w};
            #pragma unroll
            for (int i = 0; i < 8; i++) {
                unsigned long long ar = pk2(aa[i], aa[i]);
                #pragma unroll
                for (int j = 0; j < 4; j++) fma2(acc[i][j], ar, bb[j]);
            }
        }
        if (more) {
            #pragma unroll
            for (int it = 0; it < 2; it++) {
                int q = tid + it * 256;
                int row = q >> 2, kq = (q & 3) << 2;
                As[b ^ 1][kq + 0][row] = pa[it].x; As[b ^ 1][kq + 1][row] = pa[it].y;
                As[b ^ 1][kq + 2][row] = pa[it].z; As[b ^ 1][kq + 3][row] = pa[it].w;
            }
            cp_wait0();
        }
        __syncthreads();
        b ^= 1;
    }

    // epilogue: route each float4 to PA / PB / PE by column range
    #pragma unroll
    for (int i = 0; i < 8; i++) {
        int row = bm + ((i < 4) ? (tr + i) : (tr + 64 + i - 4));
        if (row >= Nn) continue;
        #pragma unroll
        for (int half = 0; half < 2; half++) {
            int colbase = bn + tc + half * 64;
            float4 v;
            upk2(acc[i][half * 2 + 0], v.x, v.y);
            upk2(acc[i][half * 2 + 1], v.z, v.w);
            if (colbase < 288) {
                *reinterpret_cast<float4*>(&g_PA[(size_t)row * 288 + colbase]) = v;
            } else if (colbase < 576) {
                *reinterpret_cast<float4*>(&g_PB[(size_t)row * 288 + colbase - 288]) = v;
            } else if (colbase == 576) {
                *reinterpret_cast<float4*>(&g_PE[(size_t)row * 4]) = v;
            }
        }
    }
}

// ---------------- CSR build ----------------------------------------------------
__global__ void deg_kernel(const int* __restrict__ dst, int E, int tbase) {
    int e = blockIdx.x * blockDim.x + threadIdx.x;
    if (e >= E) return;
    atomicAdd(&g_deg[tbase + dst[e]], 1);
}

__global__ void scan_blocks_kernel(int M) {
    __shared__ int s[256];
    int base = blockIdx.x * 4096;
    int tid = threadIdx.x;
    int vals[16];
    int sum = 0;
    #pragma unroll
    for (int i = 0; i < 16; i++) {
        int idx = base + tid * 16 + i;
        int v = (idx < M) ? g_deg[idx] : 0;
        vals[i] = sum;
        sum += v;
    }
    s[tid] = sum;
    __syncthreads();
    #pragma unroll
    for (int off = 1; off < 256; off <<= 1) {
        int t = (tid >= off) ? s[tid - off] : 0;
        __syncthreads();
        if (tid >= off) s[tid] += t;
        __syncthreads();
    }
    int excl = (tid > 0) ? s[tid - 1] : 0;
    #pragma unroll
    for (int i = 0; i < 16; i++) {
        int idx = base + tid * 16 + i;
        if (idx < M) g_start[idx] = excl + vals[i];
    }
    if (tid == 0) g_bsum[blockIdx.x] = s[255];
}

__global__ void scan_tops_kernel(int B) {
    __shared__ int s[128];
    int tid = threadIdx.x;
    s[tid] = (tid < B) ? g_bsum[tid] : 0;
    __syncthreads();
    #pragma unroll
    for (int off = 1; off < 128; off <<= 1) {
        int t = (tid >= off) ? s[tid - off] : 0;
        __syncthreads();
        if (tid >= off) s[tid] += t;
        __syncthreads();
    }
    if (tid < B) g_bsum[tid] = (tid > 0) ? s[tid - 1] : 0;
}

__global__ void scan_add_kernel(int M) {
    int i = blockIdx.x * blockDim.x + threadIdx.x;
    if (i >= M) return;
    g_start[i] += g_bsum[i >> 12];
}

__global__ void fill_kernel(const int* __restrict__ dst, int E, int tbase) {
    int e = blockIdx.x * blockDim.x + threadIdx.x;
    if (e >= E) return;
    int d = tbase + dst[e];
    int pos = atomicAdd(&g_cur[d], 1);
    g_csr[g_start[d] + pos] = e;
}

// ---------------- edge weights (gathers from 1.6MB L2-hot g_PE) ----------------
__global__ void edge_w_kernel(const int* __restrict__ src, const int* __restrict__ dst,
                              int elo, int ero, int which, int E) {
    int e = blockIdx.x * blockDim.x + threadIdx.x;
    if (e >= E) return;
    int s = src[e], d = dst[e];
    float sc = __ldg(&g_PE[(size_t)s * 4 + elo]) + __ldg(&g_PE[(size_t)d * 4 + ero]);
    sc = (sc > 0.f) ? sc : 0.01f * sc;
    float* wbuf = (which == 0) ? g_w0 : g_w1;   // resolved in device code
    wbuf[e] = expf(sc);
}

// ---------------- dst-parallel aggregation (24 threads / node / type) ----------
// Gathers hit g_PA: per-type footprint 38.4MB -> L2-resident; types processed
// in block order (g = t*Nn + n) so each slab stays hot.
__global__ void agg_kernel(const int* __restrict__ src0, const int* __restrict__ src1,
                           const int* __restrict__ src2, int Nn) {
    int gid = blockIdx.x * blockDim.x + threadIdx.x;
    int g = gid / 24;
    int c = gid % 24;
    if (g >= 3 * Nn) return;
    int t = g / Nn;
    int n = g - t * Nn;
    int start = g_start[g];
    int cnt = g_deg[g];
    const int* src = (t == 0) ? src0 : (t == 1) ? src1 : src2;
    const float* wb = (t == 0) ? g_w0 : g_w1;   // unused for t==2
    int toff = t * HH;
    int c4 = c << 2;

    float4 acc = make_float4(0.f, 0.f, 0.f, 0.f);
    float den = 0.f;
    int eid_n = 0, s_n = 0;
    if (cnt > 0) { eid_n = g_csr[start]; s_n = src[eid_n]; }
    for (int i = 0; i < cnt; i++) {
        int eid = eid_n, s = s_n;
        if (i + 1 < cnt) { eid_n = g_csr[start + i + 1]; s_n = src[eid_n]; }
        float w = (t < 2) ? __ldg(&wb[eid]) : 1.f;
        float4 a = *reinterpret_cast<const float4*>(&g_PA[(size_t)s * 288 + toff + c4]);
        acc.x += w * a.x; acc.y += w * a.y; acc.z += w * a.z; acc.w += w * a.w;
        den += w;
    }

    float4 outv = make_float4(0.f, 0.f, 0.f, 0.f);
    if (cnt > 0) {
        float r = 1.f / den;
        float4 bv = *reinterpret_cast<const float4*>(&g_PB[(size_t)n * 288 + toff + c4]);
        float4 cb = *reinterpret_cast<const float4*>(&g_CB[toff + c4]);
        outv = make_float4(acc.x * r + bv.x + cb.x, acc.y * r + bv.y + cb.y,
                           acc.z * r + bv.z + cb.z, acc.w * r + bv.w + cb.w);
    }
    *reinterpret_cast<float4*>(&g_Xm[(size_t)n * 288 + toff + c4]) = outv;
}

// ---------------- GEMM 2: out = relu([h|Xm] @ Wu + bu) (double-buffered) -------
__global__ void __launch_bounds__(256) gemm_out_kernel(const float* __restrict__ h,
                                                       const float* __restrict__ Wu,
                                                       const float* __restrict__ bu,
                                                       float* __restrict__ out, int Nn) {
    __shared__ float As[2][16][132];
    __shared__ float Bs[2][16][100];
    const int bm = blockIdx.x * 128;
    const int tid = threadIdx.x;
    const int tr = (tid >> 4) << 2;
    const int tc = (tid & 15) * 6;
    unsigned long long acc[8][3];
    #pragma unroll
    for (int i = 0; i < 8; i++)
        #pragma unroll
        for (int j = 0; j < 3; j++) acc[i][j] = 0ull;

    float4 pa[2];
    // prologue: tile 0 (cols 0..15 all come from h since 16 <= 96)
    #pragma unroll
    for (int it = 0; it < 2; it++) {
        int q = tid + it * 256;
        if (q < 384) {
            int k = q / 24;
            int c4 = (q % 24) << 2;
            cp_async16(&Bs[0][k][c4], &Wu[(size_t)k * HH + c4]);
        }
    }
    cp_commit();
    #pragma unroll
    for (int it = 0; it < 2; it++) {
        int q = tid + it * 256;
        int row = q >> 2, kq = (q & 3) << 2;
        int grow = bm + row;
        pa[it] = (grow < Nn) ? *reinterpret_cast<const float4*>(&h[(size_t)grow * HH + kq])
                             : make_float4(0.f, 0.f, 0.f, 0.f);
    }
    #pragma unroll
    for (int it = 0; it < 2; it++) {
        int q = tid + it * 256;
        int row = q >> 2, kq = (q & 3) << 2;
        As[0][kq + 0][row] = pa[it].x; As[0][kq + 1][row] = pa[it].y;
        As[0][kq + 2][row] = pa[it].z; As[0][kq + 3][row] = pa[it].w;
    }
    cp_wait0();
    __syncthreads();

    int b = 0;
    for (int k0 = 0; k0 < 384; k0 += 16) {
        bool more = (k0 + 16 < 384);
        if (more) {
            #pragma unroll
            for (int it = 0; it < 2; it++) {
                int q = tid + it * 256;
                if (q < 384) {
                    int k = q / 24;
                    int c4 = (q % 24) << 2;
                    cp_async16(&Bs[b ^ 1][k][c4], &Wu[(size_t)(k0 + 16 + k) * HH + c4]);
                }
            }
            cp_commit();
            #pragma unroll
            for (int it = 0; it < 2; it++) {
                int q = tid + it * 256;
                int row = q >> 2, kq = (q & 3) << 2;
                int grow = bm + row;
                int col = k0 + 16 + kq;
                float4 v = make_float4(0.f, 0.f, 0.f, 0.f);
                if (grow < Nn) {
                    v = (col < HH)
                      ? *reinterpret_cast<const float4*>(&h[(size_t)grow * HH + col])
                      : *reinterpret_cast<const float4*>(&g_Xm[(size_t)grow * 288 + col - HH]);
                }
                pa[it] = v;
            }
        }
        #pragma unroll
        for (int kk = 0; kk < 16; kk++) {
            float4 a0 = *reinterpret_cast<const float4*>(&As[b][kk][tr]);
            float4 a1 = *reinterpret_cast<const float4*>(&As[b][kk][tr + 64]);
            float2 b0 = *reinterpret_cast<const float2*>(&Bs[b][kk][tc]);
            float2 b1 = *reinterpret_cast<const float2*>(&Bs[b][kk][tc + 2]);
            float2 b2 = *reinterpret_cast<const float2*>(&Bs[b][kk][tc + 4]);
            unsigned long long bb[3] = {pk2(b0.x, b0.y), pk2(b1.x, b1.y), pk2(b2.x, b2.y)};
            float aa[8] = {a0.x, a0.y, a0.z, a0.w, a1.x, a1.y, a1.z, a1.w};
            #pragma unroll
            for (int i = 0; i < 8; i++) {
                unsigned long long ar = pk2(aa[i], aa[i]);
                #pragma unroll
                for (int j = 0; j < 3; j++) fma2(acc[i][j], ar, bb[j]);
            }
        }
        if (more) {
            #pragma unroll
            for (int it = 0; it < 2; it++) {
                int q = tid + it * 256;
                int row = q >> 2, kq = (q & 3) << 2;
                As[b ^ 1][kq + 0][row] = pa[it].x; As[b ^ 1][kq + 1][row] = pa[it].y;
                As[b ^ 1][kq + 2][row] = pa[it].z; As[b ^ 1][kq + 3][row] = pa[it].w;
            }
            cp_wait0();
        }
        __syncthreads();
        b ^= 1;
    }

    float bias[6];
    #pragma unroll
    for (int j = 0; j < 6; j++) bias[j] = __ldg(&bu[tc + j]);

    #pragma unroll
    for (int i = 0; i < 8; i++) {
        int row = bm + ((i < 4) ? (tr + i) : (tr + 64 + i - 4));
        if (row >= Nn) continue;
        float v[6];
        upk2(acc[i][0], v[0], v[1]);
        upk2(acc[i][1], v[2], v[3]);
        upk2(acc[i][2], v[4], v[5]);
        #pragma unroll
        for (int j = 0; j < 6; j++)
            out[(size_t)row * HH + tc + j] = fmaxf(v[j] + bias[j], 0.f);
    }
}

// ---------------- launch -------------------------------------------------------
extern "C" void kernel_launch(void* const* d_in, const int* in_sizes, int n_in,
                              void* d_out, int out_size) {
    const float* h    = (const float*)d_in[0];
    const int*   src0 = (const int*)d_in[1];
    const int*   dst0 = (const int*)d_in[2];
    const int*   src1 = (const int*)d_in[3];
    const int*   dst1 = (const int*)d_in[4];
    const int*   src2 = (const int*)d_in[5];
    const int*   dst2 = (const int*)d_in[6];
    const float* Wm0  = (const float*)d_in[7];
    const float* bm0  = (const float*)d_in[8];
    const float* ef0  = (const float*)d_in[9];
    const float* Wm1  = (const float*)d_in[10];
    const float* bm1  = (const float*)d_in[11];
    const float* ef1  = (const float*)d_in[12];
    const float* Wm2  = (const float*)d_in[13];
    const float* bm2  = (const float*)d_in[14];
    const float* ef2  = (const float*)d_in[15];
    const float* Wn0  = (const float*)d_in[16];
    const float* Wa0  = (const float*)d_in[17];
    const float* Wn1  = (const float*)d_in[18];
    const float* Wa1  = (const float*)d_in[19];
    const float* Wu   = (const float*)d_in[20];
    const float* bu   = (const float*)d_in[21];
    float* out = (float*)d_out;

    int Nn = in_sizes[0] / HH;
    int E0 = in_sizes[1];
    int E1 = in_sizes[3];
    int E2 = in_sizes[5];
    int M3 = 3 * Nn;
    int B = (M3 + 4095) / 4096;

    zero_kernel<<<256, 256>>>(M3);
    pack_w_kernel<<<(PCPAD * HH + 255) / 256, 256>>>(Wm0, Wm1, Wm2, Wn0, Wa0, Wn1, Wa1);
    pack_c_kernel<<<1, 3 * HH>>>(Wm0, bm0, ef0, Wm1, bm1, ef1, Wm2, bm2, ef2);

    // CSR build (independent of GEMM)
    deg_kernel<<<(E0 + 255) / 256, 256>>>(dst0, E0, 0);
    deg_kernel<<<(E1 + 255) / 256, 256>>>(dst1, E1, Nn);
    deg_kernel<<<(E2 + 255) / 256, 256>>>(dst2, E2, 2 * Nn);
    scan_blocks_kernel<<<B, 256>>>(M3);
    scan_tops_kernel<<<1, 128>>>(B);
    scan_add_kernel<<<(M3 + 255) / 256, 256>>>(M3);
    fill_kernel<<<(E0 + 255) / 256, 256>>>(dst0, E0, 0);
    fill_kernel<<<(E1 + 255) / 256, 256>>>(dst1, E1, Nn);
    fill_kernel<<<(E2 + 255) / 256, 256>>>(dst2, E2, 2 * Nn);

    dim3 g1(PCPAD / 128, (Nn + 127) / 128);
    gemm_p_kernel<<<g1, 256>>>(h, Nn);

    edge_w_kernel<<<(E0 + 255) / 256, 256>>>(src0, dst0, 0, 1, 0, E0);
    edge_w_kernel<<<(E1 + 255) / 256, 256>>>(src1, dst1, 2, 3, 1, E1);

    agg_kernel<<<(3 * Nn * 24 + 191) / 192, 192>>>(src0, src1, src2, Nn);

    gemm_out_kernel<<<(Nn + 127) / 128, 256>>>(h, Wu, bu, out, Nn);
}

// round 13
// speedup vs baseline: 1.1873x; 1.1873x over previous
#include <cuda_runtime.h>
#include <cstdint>
#include <cstddef>

#define NN   100000   // nodes (max)
#define HH   96       // hidden
#define AA   32       // attn dim
#define EE   500000   // edges per type (max)
#define PCP2 384      // padded GEMM col count (288 A + 4 attn + pad)

// ---------------- device scratch ----------------------------------------------
__device__ float g_PA[(size_t)NN * 288];        // A0|A1|A2 per row (gathered by agg)
__device__ float g_PE[(size_t)NN * 4];          // el0,er0,el1,er1 (L2-hot gathers)
__device__ float g_WpackT[HH * PCP2];           // k-major: [k][j]
__device__ float g_CB[3 * HH];                  // c_t
__device__ float g_F[3 * HH * HH];              // F_t = WmB_t @ Wu_t  [t][k][j]
__device__ float g_Wu2[384 * HH];               // folded Wu
__device__ float g_cvec[3 * HH];                // c_t @ Wu_t
__device__ float g_w0[EE];
__device__ float g_w1[EE];
__device__ float g_Xm[(size_t)NN * 288];        // [num0/den0 | num1/den1 | sum2/cnt2]
__device__ int   g_deg[3 * NN];
__device__ int   g_start[3 * NN];
__device__ int   g_cur[3 * NN];
__device__ int   g_bsum[128];
__device__ int   g_csr[3 * EE];

// ---------------- packed f32x2 helpers -----------------------------------------
__device__ __forceinline__ unsigned long long pk2(float lo, float hi) {
    unsigned long long r;
    asm("mov.b64 %0, {%1, %2};" : "=l"(r) : "f"(lo), "f"(hi));
    return r;
}
__device__ __forceinline__ void upk2(unsigned long long v, float& lo, float& hi) {
    asm("mov.b64 {%0, %1}, %2;" : "=f"(lo), "=f"(hi) : "l"(v));
}
__device__ __forceinline__ void fma2(unsigned long long& d, unsigned long long a, unsigned long long b) {
    asm("fma.rn.f32x2 %0, %1, %2, %3;" : "=l"(d) : "l"(a), "l"(b), "l"(d));
}
__device__ __forceinline__ void cp_async16(void* smem, const void* gmem) {
    unsigned s = (unsigned)__cvta_generic_to_shared(smem);
    asm volatile("cp.async.cg.shared.global [%0], [%1], 16;" :: "r"(s), "l"(gmem));
}
__device__ __forceinline__ void cp_commit() { asm volatile("cp.async.commit_group;"); }
__device__ __forceinline__ void cp_wait0()  { asm volatile("cp.async.wait_group 0;"); }

// ---------------- 1. zero init (deg + cur only) --------------------------------
__global__ void zero_kernel(int M3) {
    int i = blockIdx.x * blockDim.x + threadIdx.x;
    int stride = gridDim.x * blockDim.x;
    for (int k = i; k < M3; k += stride) { g_deg[k] = 0; g_cur[k] = 0; }
}

// ---------------- 2. weight packing (k-major, A|attn order, 384 padded) --------
__global__ void pack_w_kernel(const float* __restrict__ Wm0, const float* __restrict__ Wm1,
                              const float* __restrict__ Wm2,
                              const float* __restrict__ Wn0, const float* __restrict__ Wa0,
                              const float* __restrict__ Wn1, const float* __restrict__ Wa1) {
    int gid = blockIdx.x * blockDim.x + threadIdx.x;
    if (gid >= PCP2 * HH) return;
    int j = gid / HH;     // output column
    int k = gid % HH;     // input feature
    float v = 0.f;
    if (j < 288) {                      // A-blocks: src part of Wm, rows [0,96)
        int t = j / HH;
        int jj = j % HH;
        const float* Wm = (t == 0) ? Wm0 : (t == 1) ? Wm1 : Wm2;
        v = Wm[(size_t)k * HH + jj];
    } else if (j < 292) {               // attn: el0,er0,el1,er1
        int q = j - 288;
        const float* Wn = (q < 2) ? Wn0 : Wn1;
        const float* Wa = (q < 2) ? Wa0 : Wa1;
        int off = (q & 1) * AA;
        float s = 0.f;
        #pragma unroll
        for (int a = 0; a < AA; a++) s += Wn[(size_t)k * AA + a] * Wa[off + a];
        v = s;
    }
    g_WpackT[(size_t)k * PCP2 + j] = v;
}

// ---------------- 3. pack c_t = ef_t @ Wm_t[192:] + bm_t -----------------------
__global__ void pack_c_kernel(const float* __restrict__ Wm0, const float* __restrict__ bm0,
                              const float* __restrict__ ef0,
                              const float* __restrict__ Wm1, const float* __restrict__ bm1,
                              const float* __restrict__ ef1,
                              const float* __restrict__ Wm2, const float* __restrict__ bm2,
                              const float* __restrict__ ef2) {
    int gid = threadIdx.x;
    if (gid >= 3 * HH) return;
    int t = gid / HH, j = gid % HH;
    const float* Wm = (t == 0) ? Wm0 : (t == 1) ? Wm1 : Wm2;
    const float* bm = (t == 0) ? bm0 : (t == 1) ? bm1 : bm2;
    const float* ef = (t == 0) ? ef0 : (t == 1) ? ef1 : ef2;
    float s = bm[j];
    #pragma unroll
    for (int d = 0; d < 16; d++) s += ef[d] * Wm[(size_t)(192 + d) * HH + j];
    g_CB[gid] = s;
}

// ---------------- 4. F_t[k][j] = sum_m WmB_t[k][m] * Wu_t[m][j] ----------------
__global__ void fold_F_kernel(const float* __restrict__ Wm0, const float* __restrict__ Wm1,
                              const float* __restrict__ Wm2, const float* __restrict__ Wu) {
    int idx = blockIdx.x * blockDim.x + threadIdx.x;
    if (idx >= 3 * HH * HH) return;
    int t = idx / (HH * HH);
    int r = idx - t * HH * HH;
    int k = r / HH, j = r % HH;
    const float* Wm = (t == 0) ? Wm0 : (t == 1) ? Wm1 : Wm2;
    float s = 0.f;
    #pragma unroll 8
    for (int m = 0; m < HH; m++)
        s += Wm[(size_t)(HH + k) * HH + m] * Wu[(size_t)(HH + HH * t + m) * HH + j];
    g_F[idx] = s;
}

// ---------------- 5. Wu2 = Wu with h-block folded; cvec_t = c_t @ Wu_t ---------
__global__ void fold_misc_kernel(const float* __restrict__ Wu) {
    int gid = blockIdx.x * blockDim.x + threadIdx.x;
    if (gid < 384 * HH) {
        int k = gid / HH, j = gid % HH;
        float v = Wu[gid];
        if (k < HH)
            v += g_F[k * HH + j] + g_F[HH * HH + k * HH + j] + g_F[2 * HH * HH + k * HH + j];
        g_Wu2[gid] = v;
    } else if (gid < 384 * HH + 3 * HH) {
        int q = gid - 384 * HH;
        int t = q / HH, j = q % HH;
        float s = 0.f;
        #pragma unroll 8
        for (int m = 0; m < HH; m++)
            s += g_CB[t * HH + m] * Wu[(size_t)(HH + HH * t + m) * HH + j];
        g_cvec[q] = s;
    }
}

// ---------------- 6. GEMM 1: [PA|PE] = h @ Wcat (double-buffered) --------------
__global__ void __launch_bounds__(256) gemm_p_kernel(const float* __restrict__ h, int Nn) {
    __shared__ float As[2][16][132];
    __shared__ float Bs[2][16][132];
    const int bm = blockIdx.y * 128;
    const int bn = blockIdx.x * 128;
    const int tid = threadIdx.x;
    const int tr = (tid >> 4) << 2;
    const int tc = (tid & 15) << 2;
    unsigned long long acc[8][4];
    #pragma unroll
    for (int i = 0; i < 8; i++)
        #pragma unroll
        for (int j = 0; j < 4; j++) acc[i][j] = 0ull;

    float4 pa[2];
    #pragma unroll
    for (int it = 0; it < 2; it++) {
        int q = tid + it * 256;
        int k = q >> 5;
        int c4 = (q & 31) << 2;
        cp_async16(&Bs[0][k][c4], &g_WpackT[(size_t)k * PCP2 + bn + c4]);
    }
    cp_commit();
    #pragma unroll
    for (int it = 0; it < 2; it++) {
        int q = tid + it * 256;
        int row = q >> 2, kq = (q & 3) << 2;
        int grow = bm + row;
        pa[it] = (grow < Nn) ? *reinterpret_cast<const float4*>(&h[(size_t)grow * HH + kq])
                             : make_float4(0.f, 0.f, 0.f, 0.f);
    }
    #pragma unroll
    for (int it = 0; it < 2; it++) {
        int q = tid + it * 256;
        int row = q >> 2, kq = (q & 3) << 2;
        As[0][kq + 0][row] = pa[it].x; As[0][kq + 1][row] = pa[it].y;
        As[0][kq + 2][row] = pa[it].z; As[0][kq + 3][row] = pa[it].w;
    }
    cp_wait0();
    __syncthreads();

    int b = 0;
    for (int k0 = 0; k0 < HH; k0 += 16) {
        bool more = (k0 + 16 < HH);
        if (more) {
            #pragma unroll
            for (int it = 0; it < 2; it++) {
                int q = tid + it * 256;
                int k = q >> 5;
                int c4 = (q & 31) << 2;
                cp_async16(&Bs[b ^ 1][k][c4], &g_WpackT[(size_t)(k0 + 16 + k) * PCP2 + bn + c4]);
            }
            cp_commit();
            #pragma unroll
            for (int it = 0; it < 2; it++) {
                int q = tid + it * 256;
                int row = q >> 2, kq = (q & 3) << 2;
                int grow = bm + row;
                pa[it] = (grow < Nn) ? *reinterpret_cast<const float4*>(&h[(size_t)grow * HH + k0 + 16 + kq])
                                     : make_float4(0.f, 0.f, 0.f, 0.f);
            }
        }
        #pragma unroll
        for (int kk = 0; kk < 16; kk++) {
            float4 a0 = *reinterpret_cast<const float4*>(&As[b][kk][tr]);
            float4 a1 = *reinterpret_cast<const float4*>(&As[b][kk][tr + 64]);
            float4 b0 = *reinterpret_cast<const float4*>(&Bs[b][kk][tc]);
            float4 b1 = *reinterpret_cast<const float4*>(&Bs[b][kk][tc + 64]);
            unsigned long long bb[4] = {pk2(b0.x, b0.y), pk2(b0.z, b0.w),
                                        pk2(b1.x, b1.y), pk2(b1.z, b1.w)};
            float aa[8] = {a0.x, a0.y, a0.z, a0.w, a1.x, a1.y, a1.z, a1.w};
            #pragma unroll
            for (int i = 0; i < 8; i++) {
                unsigned long long ar = pk2(aa[i], aa[i]);
                #pragma unroll
                for (int j = 0; j < 4; j++) fma2(acc[i][j], ar, bb[j]);
            }
        }
        if (more) {
            #pragma unroll
            for (int it = 0; it < 2; it++) {
                int q = tid + it * 256;
                int row = q >> 2, kq = (q & 3) << 2;
                As[b ^ 1][kq + 0][row] = pa[it].x; As[b ^ 1][kq + 1][row] = pa[it].y;
                As[b ^ 1][kq + 2][row] = pa[it].z; As[b ^ 1][kq + 3][row] = pa[it].w;
            }
            cp_wait0();
        }
        __syncthreads();
        b ^= 1;
    }

    // epilogue: cols [0,288) -> PA, col 288 float4 -> PE, rest padding (dropped)
    #pragma unroll
    for (int i = 0; i < 8; i++) {
        int row = bm + ((i < 4) ? (tr + i) : (tr + 64 + i - 4));
        if (row >= Nn) continue;
        #pragma unroll
        for (int half = 0; half < 2; half++) {
            int colbase = bn + tc + half * 64;
            float4 v;
            upk2(acc[i][half * 2 + 0], v.x, v.y);
            upk2(acc[i][half * 2 + 1], v.z, v.w);
            if (colbase < 288) {
                *reinterpret_cast<float4*>(&g_PA[(size_t)row * 288 + colbase]) = v;
            } else if (colbase == 288) {
                *reinterpret_cast<float4*>(&g_PE[(size_t)row * 4]) = v;
            }
        }
    }
}

// ---------------- CSR build ----------------------------------------------------
__global__ void deg_kernel(const int* __restrict__ dst, int E, int tbase) {
    int e = blockIdx.x * blockDim.x + threadIdx.x;
    if (e >= E) return;
    atomicAdd(&g_deg[tbase + dst[e]], 1);
}

__global__ void scan_blocks_kernel(int M) {
    __shared__ int s[256];
    int base = blockIdx.x * 4096;
    int tid = threadIdx.x;
    int vals[16];
    int sum = 0;
    #pragma unroll
    for (int i = 0; i < 16; i++) {
        int idx = base + tid * 16 + i;
        int v = (idx < M) ? g_deg[idx] : 0;
        vals[i] = sum;
        sum += v;
    }
    s[tid] = sum;
    __syncthreads();
    #pragma unroll
    for (int off = 1; off < 256; off <<= 1) {
        int t = (tid >= off) ? s[tid - off] : 0;
        __syncthreads();
        if (tid >= off) s[tid] += t;
        __syncthreads();
    }
    int excl = (tid > 0) ? s[tid - 1] : 0;
    #pragma unroll
    for (int i = 0; i < 16; i++) {
        int idx = base + tid * 16 + i;
        if (idx < M) g_start[idx] = excl + vals[i];
    }
    if (tid == 0) g_bsum[blockIdx.x] = s[255];
}

__global__ void scan_tops_kernel(int B) {
    __shared__ int s[128];
    int tid = threadIdx.x;
    s[tid] = (tid < B) ? g_bsum[tid] : 0;
    __syncthreads();
    #pragma unroll
    for (int off = 1; off < 128; off <<= 1) {
        int t = (tid >= off) ? s[tid - off] : 0;
        __syncthreads();
        if (tid >= off) s[tid] += t;
        __syncthreads();
    }
    if (tid < B) g_bsum[tid] = (tid > 0) ? s[tid - 1] : 0;
}

__global__ void scan_add_kernel(int M) {
    int i = blockIdx.x * blockDim.x + threadIdx.x;
    if (i >= M) return;
    g_start[i] += g_bsum[i >> 12];
}

__global__ void fill_kernel(const int* __restrict__ dst, int E, int tbase) {
    int e = blockIdx.x * blockDim.x + threadIdx.x;
    if (e >= E) return;
    int d = tbase + dst[e];
    int pos = atomicAdd(&g_cur[d], 1);
    g_csr[g_start[d] + pos] = e;
}

// ---------------- edge weights (gathers from 1.6MB L2-hot g_PE) ----------------
__global__ void edge_w_kernel(const int* __restrict__ src, const int* __restrict__ dst,
                              int elo, int ero, int which, int E) {
    int e = blockIdx.x * blockDim.x + threadIdx.x;
    if (e >= E) return;
    int s = src[e], d = dst[e];
    float sc = __ldg(&g_PE[(size_t)s * 4 + elo]) + __ldg(&g_PE[(size_t)d * 4 + ero]);
    sc = (sc > 0.f) ? sc : 0.01f * sc;
    float* wbuf = (which == 0) ? g_w0 : g_w1;   // resolved in device code
    wbuf[e] = expf(sc);
}

// ---------------- dst-parallel aggregation (num/den only; B+c folded into Wu2) -
__global__ void agg_kernel(const int* __restrict__ src0, const int* __restrict__ src1,
                           const int* __restrict__ src2, int Nn) {
    int gid = blockIdx.x * blockDim.x + threadIdx.x;
    int g = gid / 24;
    int c = gid % 24;
    if (g >= 3 * Nn) return;
    int t = g / Nn;
    int n = g - t * Nn;
    int start = g_start[g];
    int cnt = g_deg[g];
    const int* src = (t == 0) ? src0 : (t == 1) ? src1 : src2;
    const float* wb = (t == 0) ? g_w0 : g_w1;   // unused for t==2
    int toff = t * HH;
    int c4 = c << 2;

    float4 acc = make_float4(0.f, 0.f, 0.f, 0.f);
    float den = 0.f;
    int eid_n = 0, s_n = 0;
    if (cnt > 0) { eid_n = g_csr[start]; s_n = src[eid_n]; }
    for (int i = 0; i < cnt; i++) {
        int eid = eid_n, s = s_n;
        if (i + 1 < cnt) { eid_n = g_csr[start + i + 1]; s_n = src[eid_n]; }
        float w = (t < 2) ? __ldg(&wb[eid]) : 1.f;
        float4 a = *reinterpret_cast<const float4*>(&g_PA[(size_t)s * 288 + toff + c4]);
        acc.x += w * a.x; acc.y += w * a.y; acc.z += w * a.z; acc.w += w * a.w;
        den += w;
    }

    float4 outv = make_float4(0.f, 0.f, 0.f, 0.f);
    if (cnt > 0) {
        float r = 1.f / den;
        outv = make_float4(acc.x * r, acc.y * r, acc.z * r, acc.w * r);
    }
    *reinterpret_cast<float4*>(&g_Xm[(size_t)n * 288 + toff + c4]) = outv;
}

// ---------------- GEMM 2: out = relu([h|Xm] @ Wu2 + bu + Σcvec) ----------------
// For rare (row,type) with deg==0 the fold over-counts: subtract h@F_t + cvec_t.
__global__ void __launch_bounds__(256) gemm_out_kernel(const float* __restrict__ h,
                                                       const float* __restrict__ bu,
                                                       float* __restrict__ out, int Nn) {
    __shared__ float As[2][16][132];
    __shared__ float Bs[2][16][100];
    const int bm = blockIdx.x * 128;
    const int tid = threadIdx.x;
    const int tr = (tid >> 4) << 2;
    const int tc = (tid & 15) * 6;
    unsigned long long acc[8][3];
    #pragma unroll
    for (int i = 0; i < 8; i++)
        #pragma unroll
        for (int j = 0; j < 3; j++) acc[i][j] = 0ull;

    float4 pa[2];
    // prologue: tile 0 (cols 0..15 all come from h since 16 <= 96)
    #pragma unroll
    for (int it = 0; it < 2; it++) {
        int q = tid + it * 256;
        if (q < 384) {
            int k = q / 24;
            int c4 = (q % 24) << 2;
            cp_async16(&Bs[0][k][c4], &g_Wu2[(size_t)k * HH + c4]);
        }
    }
    cp_commit();
    #pragma unroll
    for (int it = 0; it < 2; it++) {
        int q = tid + it * 256;
        int row = q >> 2, kq = (q & 3) << 2;
        int grow = bm + row;
        pa[it] = (grow < Nn) ? *reinterpret_cast<const float4*>(&h[(size_t)grow * HH + kq])
                             : make_float4(0.f, 0.f, 0.f, 0.f);
    }
    #pragma unroll
    for (int it = 0; it < 2; it++) {
        int q = tid + it * 256;
        int row = q >> 2, kq = (q & 3) << 2;
        As[0][kq + 0][row] = pa[it].x; As[0][kq + 1][row] = pa[it].y;
        As[0][kq + 2][row] = pa[it].z; As[0][kq + 3][row] = pa[it].w;
    }
    cp_wait0();
    __syncthreads();

    int b = 0;
    for (int k0 = 0; k0 < 384; k0 += 16) {
        bool more = (k0 + 16 < 384);
        if (more) {
            #pragma unroll
            for (int it = 0; it < 2; it++) {
                int q = tid + it * 256;
                if (q < 384) {
                    int k = q / 24;
                    int c4 = (q % 24) << 2;
                    cp_async16(&Bs[b ^ 1][k][c4], &g_Wu2[(size_t)(k0 + 16 + k) * HH + c4]);
                }
            }
            cp_commit();
            #pragma unroll
            for (int it = 0; it < 2; it++) {
                int q = tid + it * 256;
                int row = q >> 2, kq = (q & 3) << 2;
                int grow = bm + row;
                int col = k0 + 16 + kq;
                float4 v = make_float4(0.f, 0.f, 0.f, 0.f);
                if (grow < Nn) {
                    v = (col < HH)
                      ? *reinterpret_cast<const float4*>(&h[(size_t)grow * HH + col])
                      : *reinterpret_cast<const float4*>(&g_Xm[(size_t)grow * 288 + col - HH]);
                }
                pa[it] = v;
            }
        }
        #pragma unroll
        for (int kk = 0; kk < 16; kk++) {
            float4 a0 = *reinterpret_cast<const float4*>(&As[b][kk][tr]);
            float4 a1 = *reinterpret_cast<const float4*>(&As[b][kk][tr + 64]);
            float2 b0 = *reinterpret_cast<const float2*>(&Bs[b][kk][tc]);
            float2 b1 = *reinterpret_cast<const float2*>(&Bs[b][kk][tc + 2]);
            float2 b2 = *reinterpret_cast<const float2*>(&Bs[b][kk][tc + 4]);
            unsigned long long bb[3] = {pk2(b0.x, b0.y), pk2(b1.x, b1.y), pk2(b2.x, b2.y)};
            float aa[8] = {a0.x, a0.y, a0.z, a0.w, a1.x, a1.y, a1.z, a1.w};
            #pragma unroll
            for (int i = 0; i < 8; i++) {
                unsigned long long ar = pk2(aa[i], aa[i]);
                #pragma unroll
                for (int j = 0; j < 3; j++) fma2(acc[i][j], ar, bb[j]);
            }
        }
        if (more) {
            #pragma unroll
            for (int it = 0; it < 2; it++) {
                int q = tid + it * 256;
                int row = q >> 2, kq = (q & 3) << 2;
                As[b ^ 1][kq + 0][row] = pa[it].x; As[b ^ 1][kq + 1][row] = pa[it].y;
                As[b ^ 1][kq + 2][row] = pa[it].z; As[b ^ 1][kq + 3][row] = pa[it].w;
            }
            cp_wait0();
        }
        __syncthreads();
        b ^= 1;
    }

    float bias[6];
    #pragma unroll
    for (int j = 0; j < 6; j++)
        bias[j] = __ldg(&bu[tc + j]) + g_cvec[tc + j] + g_cvec[HH + tc + j] + g_cvec[2 * HH + tc + j];

    #pragma unroll
    for (int i = 0; i < 8; i++) {
        int row = bm + ((i < 4) ? (tr + i) : (tr + 64 + i - 4));
        if (row >= Nn) continue;
        float v[6];
        upk2(acc[i][0], v[0], v[1]);
        upk2(acc[i][1], v[2], v[3]);
        upk2(acc[i][2], v[4], v[5]);
        #pragma unroll
        for (int j = 0; j < 6; j++) v[j] += bias[j];

        // rare correction: for types with deg==0 the fold added h@F_t + cvec_t; remove it
        int d0 = g_deg[row], d1 = g_deg[Nn + row], d2 = g_deg[2 * Nn + row];
        if ((d0 == 0) || (d1 == 0) || (d2 == 0)) {
            for (int t = 0; t < 3; t++) {
                int dt = (t == 0) ? d0 : (t == 1) ? d1 : d2;
                if (dt != 0) continue;
                const float* Ft = &g_F[t * HH * HH];
                for (int k = 0; k < HH; k++) {
                    float hv = h[(size_t)row * HH + k];
                    #pragma unroll
                    for (int j = 0; j < 6; j++) v[j] -= hv * Ft[k * HH + tc + j];
                }
                #pragma unroll
                for (int j = 0; j < 6; j++) v[j] -= g_cvec[t * HH + tc + j];
            }
        }

        #pragma unroll
        for (int j = 0; j < 6; j++)
            out[(size_t)row * HH + tc + j] = fmaxf(v[j], 0.f);
    }
}

// ---------------- launch -------------------------------------------------------
extern "C" void kernel_launch(void* const* d_in, const int* in_sizes, int n_in,
                              void* d_out, int out_size) {
    const float* h    = (const float*)d_in[0];
    const int*   src0 = (const int*)d_in[1];
    const int*   dst0 = (const int*)d_in[2];
    const int*   src1 = (const int*)d_in[3];
    const int*   dst1 = (const int*)d_in[4];
    const int*   src2 = (const int*)d_in[5];
    const int*   dst2 = (const int*)d_in[6];
    const float* Wm0  = (const float*)d_in[7];
    const float* bm0  = (const float*)d_in[8];
    const float* ef0  = (const float*)d_in[9];
    const float* Wm1  = (const float*)d_in[10];
    const float* bm1  = (const float*)d_in[11];
    const float* ef1  = (const float*)d_in[12];
    const float* Wm2  = (const float*)d_in[13];
    const float* bm2  = (const float*)d_in[14];
    const float* ef2  = (const float*)d_in[15];
    const float* Wn0  = (const float*)d_in[16];
    const float* Wa0  = (const float*)d_in[17];
    const float* Wn1  = (const float*)d_in[18];
    const float* Wa1  = (const float*)d_in[19];
    const float* Wu   = (const float*)d_in[20];
    const float* bu   = (const float*)d_in[21];
    float* out = (float*)d_out;

    int Nn = in_sizes[0] / HH;
    int E0 = in_sizes[1];
    int E1 = in_sizes[3];
    int E2 = in_sizes[5];
    int M3 = 3 * Nn;
    int B = (M3 + 4095) / 4096;

    // launches 1-5 (so gemm_p is launch #6 -> captured by ncu -s 5 -c 1)
    zero_kernel<<<256, 256>>>(M3);
    pack_w_kernel<<<(PCP2 * HH + 255) / 256, 256>>>(Wm0, Wm1, Wm2, Wn0, Wa0, Wn1, Wa1);
    pack_c_kernel<<<1, 3 * HH>>>(Wm0, bm0, ef0, Wm1, bm1, ef1, Wm2, bm2, ef2);
    fold_F_kernel<<<(3 * HH * HH + 255) / 256, 256>>>(Wm0, Wm1, Wm2, Wu);
    fold_misc_kernel<<<(384 * HH + 3 * HH + 255) / 256, 256>>>(Wu);

    // launch 6: the big GEMM
    dim3 g1(PCP2 / 128, (Nn + 127) / 128);
    gemm_p_kernel<<<g1, 256>>>(h, Nn);

    // CSR build
    deg_kernel<<<(E0 + 255) / 256, 256>>>(dst0, E0, 0);
    deg_kernel<<<(E1 + 255) / 256, 256>>>(dst1, E1, Nn);
    deg_kernel<<<(E2 + 255) / 256, 256>>>(dst2, E2, 2 * Nn);
    scan_blocks_kernel<<<B, 256>>>(M3);
    scan_tops_kernel<<<1, 128>>>(B);
    scan_add_kernel<<<(M3 + 255) / 256, 256>>>(M3);
    fill_kernel<<<(E0 + 255) / 256, 256>>>(dst0, E0, 0);
    fill_kernel<<<(E1 + 255) / 256, 256>>>(dst1, E1, Nn);
    fill_kernel<<<(E2 + 255) / 256, 256>>>(dst2, E2, 2 * Nn);

    edge_w_kernel<<<(E0 + 255) / 256, 256>>>(src0, dst0, 0, 1, 0, E0);
    edge_w_kernel<<<(E1 + 255) / 256, 256>>>(src1, dst1, 2, 3, 1, E1);

    agg_kernel<<<(3 * Nn * 24 + 191) / 192, 192>>>(src0, src1, src2, Nn);

    gemm_out_kernel<<<(Nn + 127) / 128, 256>>>(h, bu, out, Nn);
}